// round 1
// baseline (speedup 1.0000x reference)
#include <cuda_runtime.h>
#include <cstdint>

// FANSNeuralOutputUpdate on GB300 (sm_103a).
// Structure: y[b,g] = tanh(z[b,g] @ W1[g] + b1[g]) @ W2[g] + b2[g]
// sel_idx[g] == sel_idx[g+32]  =>  pack group pair (g, g+32) into f32x2 lanes
// and use Blackwell fma.rn.f32x2 (FFMA2) to halve FMA-pipe instruction count.
// tanh via ex2+rcp (accurate ~1e-6), expected MUFU-pipe bound.

#define B_TILE     128   // batches per block
#define GP_BLOCK   8     // group-pairs per block (warp w handles pair (gp0+w, gp0+w+32))
#define NB         4     // batches per thread (lane + 32*j)
#define THREADS    256

typedef unsigned long long ull;

__device__ __forceinline__ ull pack2(float lo, float hi) {
    ull r; asm("mov.b64 %0, {%1, %2};" : "=l"(r) : "f"(lo), "f"(hi)); return r;
}
__device__ __forceinline__ void unpack2(ull v, float& lo, float& hi) {
    asm("mov.b64 {%0, %1}, %2;" : "=f"(lo), "=f"(hi) : "l"(v));
}
__device__ __forceinline__ ull ffma2(ull a, ull b, ull c) {
    ull d; asm("fma.rn.f32x2 %0, %1, %2, %3;" : "=l"(d) : "l"(a), "l"(b), "l"(c)); return d;
}

// Accurate fast tanh: tanh(x) = 1 - 2/(e^{2x}+1).
// ex2.approx + rcp.approx are both ~2^-22 accurate -> overall err ~1e-6.
// Graceful saturation at both ends, no overflow for |x| < 40.
__device__ __forceinline__ float fast_tanh(float x) {
    float e, r;
    asm("ex2.approx.f32 %0, %1;" : "=f"(e) : "f"(x * 2.885390081777927f)); // 2*log2(e)
    asm("rcp.approx.f32 %0, %1;" : "=f"(r) : "f"(e + 1.0f));
    return fmaf(-2.0f, r, 1.0f);
}

__global__ __launch_bounds__(THREADS, 2)
void fans_kernel(const float* __restrict__ x_f,   // (B,16)
                 const float* __restrict__ x_b,   // (B,16)
                 const int*   __restrict__ sel_idx, // (64,8)
                 const float* __restrict__ W1,    // (64,8,32)
                 const float* __restrict__ b1,    // (64,32)
                 const float* __restrict__ W2,    // (64,32,1)
                 const float* __restrict__ b2,    // (64,1)
                 float*       __restrict__ out,   // (B,64)
                 int Btot)
{
    __shared__ float xs[B_TILE * 33];          // padded stride 33 -> conflict-free
    __shared__ ull   wp [GP_BLOCK][8][32];     // packed {W1[g], W1[g+32]}
    __shared__ ull   b1p[GP_BLOCK][32];
    __shared__ ull   w2p[GP_BLOCK][32];
    __shared__ int   sels[GP_BLOCK][8];
    __shared__ ull   b2p[GP_BLOCK];
    __shared__ float ys[B_TILE * 17];          // padded stride 17 -> conflict-free

    const int tid    = threadIdx.x;
    const int batch0 = blockIdx.x * B_TILE;
    const int gp0    = blockIdx.y * GP_BLOCK;

    // ---- stage x tile (fully coalesced) ----
    for (int i = tid; i < B_TILE * 32; i += THREADS) {
        int bl = i >> 5, j = i & 31;
        int bg = batch0 + bl;
        float v = 0.0f;
        if (bg < Btot)
            v = (j < 16) ? x_f[bg * 16 + j] : x_b[bg * 16 + (j - 16)];
        xs[bl * 33 + j] = v;
    }
    // ---- stage packed weights for this block's 8 group-pairs ----
    for (int i = tid; i < GP_BLOCK * 8 * 32; i += THREADS) {
        int gpl = i >> 8, r = i & 255;
        int k = r >> 5, h = r & 31;
        int gA = gp0 + gpl, gB = gA + 32;
        wp[gpl][k][h] = pack2(W1[(gA * 8 + k) * 32 + h], W1[(gB * 8 + k) * 32 + h]);
    }
    for (int i = tid; i < GP_BLOCK * 32; i += THREADS) {
        int gpl = i >> 5, h = i & 31;
        int gA = gp0 + gpl, gB = gA + 32;
        b1p[gpl][h] = pack2(b1[gA * 32 + h], b1[gB * 32 + h]);
        w2p[gpl][h] = pack2(W2[gA * 32 + h], W2[gB * 32 + h]);
    }
    if (tid < GP_BLOCK * 8) {
        int gpl = tid >> 3, k = tid & 7;
        sels[gpl][k] = sel_idx[(gp0 + gpl) * 8 + k];   // sel[g] == sel[g+32]
    }
    if (tid < GP_BLOCK)
        b2p[tid] = pack2(b2[gp0 + tid], b2[gp0 + tid + 32]);
    __syncthreads();

    const int wid = tid >> 5, lane = tid & 31;

    // ---- load z into registers, duplicated into both f32x2 halves ----
    int col[8];
#pragma unroll
    for (int k = 0; k < 8; k++) col[k] = sels[wid][k];

    ull z2[NB][8];
#pragma unroll
    for (int j = 0; j < NB; j++) {
        const float* row = &xs[(lane + 32 * j) * 33];
#pragma unroll
        for (int k = 0; k < 8; k++) {
            float v = row[col[k]];
            z2[j][k] = pack2(v, v);
        }
    }

    ull y2[NB];
    ull b2v = b2p[wid];
#pragma unroll
    for (int j = 0; j < NB; j++) y2[j] = b2v;

    // ---- main loop over hidden units ----
#pragma unroll 2
    for (int h = 0; h < 32; h++) {
        ull wk[8];
#pragma unroll
        for (int k = 0; k < 8; k++) wk[k] = wp[wid][k][h];  // uniform LDS.64 broadcast
        ull accinit = b1p[wid][h];
        ull w2k     = w2p[wid][h];
#pragma unroll
        for (int j = 0; j < NB; j++) {
            ull acc = accinit;
#pragma unroll
            for (int k = 0; k < 8; k++)
                acc = ffma2(z2[j][k], wk[k], acc);   // {g, g+32} in one FFMA2
            float a, b;
            unpack2(acc, a, b);
            float ta = fast_tanh(a);
            float tb = fast_tanh(b);
            y2[j] = ffma2(pack2(ta, tb), w2k, y2[j]);
        }
    }

    // ---- stage results, then write out as full 32B sectors ----
#pragma unroll
    for (int j = 0; j < NB; j++) {
        int bl = lane + 32 * j;
        float a, b;
        unpack2(y2[j], a, b);
        ys[bl * 17 + wid]     = a;   // column gp0+wid
        ys[bl * 17 + 8 + wid] = b;   // column gp0+wid+32
    }
    __syncthreads();

    for (int e = tid; e < B_TILE * 16; e += THREADS) {
        int bl = e >> 4, c = e & 15;
        int bg = batch0 + bl;
        if (bg < Btot) {
            int colg = gp0 + ((c < 8) ? c : (c + 24));  // c>=8 -> gp0+32+(c-8)
            out[bg * 64 + colg] = ys[bl * 17 + c];
        }
    }
}

extern "C" void kernel_launch(void* const* d_in, const int* in_sizes, int n_in,
                              void* d_out, int out_size)
{
    const float* x_f = (const float*)d_in[0];
    const float* x_b = (const float*)d_in[1];
    const int*   sel = (const int*)  d_in[2];
    const float* W1  = (const float*)d_in[3];
    const float* b1  = (const float*)d_in[4];
    const float* W2  = (const float*)d_in[5];
    const float* b2  = (const float*)d_in[6];
    float*       out = (float*)d_out;

    int Btot = in_sizes[0] / 16;                 // 65536
    dim3 grid((Btot + B_TILE - 1) / B_TILE, 64 / (2 * GP_BLOCK));  // (512, 4)
    fans_kernel<<<grid, THREADS>>>(x_f, x_b, sel, W1, b1, W2, b2, out, Btot);
}